// round 15
// baseline (speedup 1.0000x reference)
#include <cuda_runtime.h>
#include <cuda_bf16.h>
#include <mma.h>
#include <cstdint>
using namespace nvcuda;

#define T_ 8
#define N_ 1024
#define D_ 128
#define JC_ 4                    // j-chunks (split of the attention j loop)
static constexpr float SCALE = 0.08838834764831845f; // 1/sqrt(128)

// ---- scratch (__device__ globals; no allocation allowed) ----
__device__ __align__(16) __nv_bfloat16 g_Xh[T_ * N_ * D_];            // 2 MB
__device__ __align__(16) unsigned      g_adjp[N_ * (N_ / 32)];        // 128 KB bitmask
__device__ __align__(16) float         g_Opart[JC_ * T_ * N_ * D_];   // 16 MB partial numerators (L2-resident)
__device__ __align__(16) float         g_lpart[JC_ * T_ * N_];        // 128 KB partial denominators
__device__ __align__(16) float         g_SW[N_ * T_ * T_];            // 256 KB sigmoid weights

// ---------------- PTX helpers ----------------
__device__ __forceinline__ uint32_t smaddr(const void* p) {
    return (uint32_t)__cvta_generic_to_shared(p);
}
__device__ __forceinline__ void cpa16(uint32_t dst, const void* src) {
    asm volatile("cp.async.cg.shared.global [%0], [%1], 16;" :: "r"(dst), "l"(src));
}
__device__ __forceinline__ void cpa_commit() { asm volatile("cp.async.commit_group;"); }
template <int NN> __device__ __forceinline__ void cpa_wait() {
    asm volatile("cp.async.wait_group %0;" :: "n"(NN));
}
__device__ __forceinline__ void ldsm4(uint32_t& r0, uint32_t& r1, uint32_t& r2, uint32_t& r3,
                                      uint32_t a) {
    asm volatile("ldmatrix.sync.aligned.m8n8.x4.shared.b16 {%0,%1,%2,%3},[%4];"
                 : "=r"(r0), "=r"(r1), "=r"(r2), "=r"(r3) : "r"(a));
}
__device__ __forceinline__ void mma16816(float* c, uint32_t a0, uint32_t a1, uint32_t a2,
                                         uint32_t a3, uint32_t b0, uint32_t b1) {
    asm volatile("mma.sync.aligned.m16n8k16.row.col.f32.bf16.bf16.f32 "
                 "{%0,%1,%2,%3}, {%4,%5,%6,%7}, {%8,%9}, {%0,%1,%2,%3};"
                 : "+f"(c[0]), "+f"(c[1]), "+f"(c[2]), "+f"(c[3])
                 : "r"(a0), "r"(a1), "r"(a2), "r"(a3), "r"(b0), "r"(b1));
}

// ---------------- K0: fp32 -> bf16 cast ----------------
__global__ void k_cast(const float* __restrict__ x) {
    int i = blockIdx.x * blockDim.x + threadIdx.x;
    if (i < T_ * N_ * D_) g_Xh[i] = __float2bfloat16(x[i]);
}

// ---------------- K0b: pack adj into bitmask ----------------
__global__ void k_pack(const int* __restrict__ adj) {
    int idx = blockIdx.x * blockDim.x + threadIdx.x;   // over N*N
    unsigned m = __ballot_sync(~0u, adj[idx] > 0);
    if ((threadIdx.x & 31) == 0) g_adjp[idx >> 5] = m;
}

// ---------------- K1: fused partial attention (proven; epilogue stores now L2-resident) ----------------
#define SM_XJ0  17408
#define SM_XJ1  34816
#define SM_P    52224
#define SM_ADJ  61440
#define SM_TOT  63488

__global__ void __launch_bounds__(128, 3) k_attn() {
    extern __shared__ char smraw[];
    __nv_bfloat16* Xms  = (__nv_bfloat16*)smraw;
    __nv_bfloat16* Xj0  = (__nv_bfloat16*)(smraw + SM_XJ0);
    __nv_bfloat16* Xj1  = (__nv_bfloat16*)(smraw + SM_XJ1);
    __nv_bfloat16* Pts  = (__nv_bfloat16*)(smraw + SM_P);
    unsigned*      adjs = (unsigned*)(smraw + SM_ADJ);
    float*         Osm  = (float*)smraw;    // epilogue only
    uint32_t smXm  = smaddr(smraw);
    uint32_t smXj0 = smXm + SM_XJ0;
    uint32_t smXj1 = smXm + SM_XJ1;

    int m0 = blockIdx.x * 64;
    int jc = blockIdx.y;
    int t  = blockIdx.z;
    int jbase = jc * (N_ / JC_);            // 256-wide chunk
    int tid = threadIdx.x;
    int w    = tid >> 5;
    int lane = tid & 31;
    const __nv_bfloat16* Xt = g_Xh + (size_t)t * N_ * D_;

    // ---- issue cp.async for j-tile 0 FIRST (overlap with Xm fill) ----
    #pragma unroll
    for (int q = 0; q < 8; q++) {           // 1024 uint4 = full 64x128 tile
        int idx = tid + q * 128;
        int r = idx >> 4, c = (idx & 15) * 8;
        cpa16(smXj0 + (uint32_t)(r * 136 + c) * 2, &Xt[(jbase + r) * D_ + c]);
    }
    cpa_commit();

    // ---- load Xm tile (plain) + adj bits ----
    #pragma unroll
    for (int q = 0; q < 8; q++) {
        int idx = tid + q * 128;            // 1024 uint4
        int r = idx >> 4, c = (idx & 15) * 8;
        *(uint4*)&Xms[r * 136 + c] = *(const uint4*)&Xt[(m0 + r) * D_ + c];
    }
    #pragma unroll
    for (int q = 0; q < 4; q++) {
        int i = tid + q * 128;              // 512 words
        adjs[i] = g_adjp[(m0 + (i >> 3)) * 32 + jc * 8 + (i & 7)];
    }

    // ---- per-thread fragment constants ----
    int gr = lane >> 2, tc = lane & 3;      // C-frag: rows gr/gr+8, cols 2tc/2tc+1
    int lrow  = lane & 15;
    int lcol8 = 8 * (lane >> 4);
    uint32_t aoffA    = (uint32_t)((16 * w + lrow) * 136 + lcol8) * 2;
    uint32_t aoffBrow = (uint32_t)(lrow * 136 + lcol8) * 2;

    wmma::fragment<wmma::accumulator, 16, 16, 16, float> oacc[4][2];
    #pragma unroll
    for (int a = 0; a < 4; a++)
        #pragma unroll
        for (int b = 0; b < 2; b++) wmma::fill_fragment(oacc[a][b], 0.0f);

    float rs0 = 0.f, rs1 = 0.f;
    const int NIT = (N_ / JC_) / 64;        // 4 j-tiles per chunk

    #pragma unroll 1
    for (int it = 0; it < NIT; it++) {
        uint32_t XJ = (it & 1) ? smXj1 : smXj0;
        __nv_bfloat16* XJp = (it & 1) ? Xj1 : Xj0;
        if (it + 1 < NIT) {
            uint32_t XJn = (it & 1) ? smXj0 : smXj1;
            int j0n = jbase + (it + 1) * 64;
            #pragma unroll
            for (int q = 0; q < 8; q++) {   // FULL 1024 uint4
                int idx = tid + q * 128;
                int r = idx >> 4, c = (idx & 15) * 8;
                cpa16(XJn + (uint32_t)(r * 136 + c) * 2, &Xt[(j0n + r) * D_ + c]);
            }
            cpa_commit();
            cpa_wait<1>();
        } else {
            cpa_wait<0>();
        }
        __syncthreads();

        // ---- QK: S(16x64) in registers ----
        float s[8][4];
        #pragma unroll
        for (int nb = 0; nb < 8; nb++)
            #pragma unroll
            for (int k = 0; k < 4; k++) s[nb][k] = 0.0f;

        #pragma unroll
        for (int ks = 0; ks < 8; ks++) {
            int k0 = ks * 16;
            uint32_t a0, a1, a2, a3;
            ldsm4(a0, a1, a2, a3, smXm + aoffA + (uint32_t)k0 * 2);
            #pragma unroll
            for (int p = 0; p < 4; p++) {
                uint32_t q0, q1, q2, q3;
                ldsm4(q0, q1, q2, q3, XJ + aoffBrow + (uint32_t)(16 * p * 136 + k0) * 2);
                mma16816(s[2 * p],     a0, a1, a2, a3, q0, q2);
                mma16816(s[2 * p + 1], a0, a1, a2, a3, q1, q3);
            }
        }

        // ---- mask + exp + rowsum; P -> smem ----
        {
            int rowE = 16 * w + gr;
            int ar0 = rowE * 8 + it * 2;
            int ar1 = (rowE + 8) * 8 + it * 2;
            unsigned w0a = adjs[ar0], w0b = adjs[ar0 + 1];
            unsigned w1a = adjs[ar1], w1b = adjs[ar1 + 1];
            #pragma unroll
            for (int nb = 0; nb < 8; nb++) {
                int col = 8 * nb + 2 * tc;
                unsigned wa = (nb < 4) ? w0a : w0b;
                unsigned wb = (nb < 4) ? w1a : w1b;
                int sh = col & 31;
                float e0 = ((wa >> sh) & 1u)       ? __expf(fminf(s[nb][0] * SCALE, 30.f)) : 0.f;
                float e1 = ((wa >> (sh + 1)) & 1u) ? __expf(fminf(s[nb][1] * SCALE, 30.f)) : 0.f;
                float f0 = ((wb >> sh) & 1u)       ? __expf(fminf(s[nb][2] * SCALE, 30.f)) : 0.f;
                float f1 = ((wb >> (sh + 1)) & 1u) ? __expf(fminf(s[nb][3] * SCALE, 30.f)) : 0.f;
                rs0 += e0 + e1;
                rs1 += f0 + f1;
                *(__nv_bfloat162*)&Pts[rowE * 72 + col]       = __floats2bfloat162_rn(e0, e1);
                *(__nv_bfloat162*)&Pts[(rowE + 8) * 72 + col] = __floats2bfloat162_rn(f0, f1);
            }
        }
        __syncthreads();

        // ---- AV: O[:, 32w:+32] += P . Xj ----
        #pragma unroll
        for (int kk = 0; kk < 4; kk++) {
            wmma::fragment<wmma::matrix_b, 16, 16, 16, __nv_bfloat16, wmma::row_major> b0, b1;
            wmma::load_matrix_sync(b0, &XJp[(kk * 16) * 136 + 32 * w], 136);
            wmma::load_matrix_sync(b1, &XJp[(kk * 16) * 136 + 32 * w + 16], 136);
            #pragma unroll
            for (int rr = 0; rr < 4; rr++) {
                wmma::fragment<wmma::matrix_a, 16, 16, 16, __nv_bfloat16, wmma::row_major> af;
                wmma::load_matrix_sync(af, &Pts[(16 * rr) * 72 + kk * 16], 72);
                wmma::mma_sync(oacc[rr][0], af, b0, oacc[rr][0]);
                wmma::mma_sync(oacc[rr][1], af, b1, oacc[rr][1]);
            }
        }
        __syncthreads();
    }

    // ---- epilogue ----
    rs0 += __shfl_xor_sync(~0u, rs0, 1); rs0 += __shfl_xor_sync(~0u, rs0, 2);
    rs1 += __shfl_xor_sync(~0u, rs1, 1); rs1 += __shfl_xor_sync(~0u, rs1, 2);
    if (tc == 0) {
        int lbase = (jc * T_ + t) * N_ + m0;
        g_lpart[lbase + 16 * w + gr]     = rs0;
        g_lpart[lbase + 16 * w + gr + 8] = rs1;
    }
    #pragma unroll
    for (int rr = 0; rr < 4; rr++)
        #pragma unroll
        for (int cc = 0; cc < 2; cc++)
            wmma::store_matrix_sync(&Osm[(16 * rr) * 132 + 32 * w + 16 * cc],
                                    oacc[rr][cc], 132, wmma::mem_row_major);
    __syncthreads();
    // PLAIN stores: g_Opart is re-read by k_sw and fits in L2 (16 MB << 126 MB).
    // __stcs here was evicting it to DRAM and starving k_sw (R10 lesson).
    float* Oout = g_Opart + ((size_t)(jc * T_ + t) * N_ + m0) * D_;
    #pragma unroll
    for (int q = 0; q < 16; q++) {
        int f4 = tid + q * 128;             // 2048 float4
        int r = f4 >> 5, c4 = (f4 & 31) * 4;
        const float* src = &Osm[r * 132 + c4];
        *(float4*)&Oout[r * D_ + c4] = make_float4(src[0], src[1], src[2], src[3]);
    }
}

// ---------------- K2a: reduce + normalize + Gram + sigmoid -> g_SW ----------------
// 512 blocks x 512 threads, TWO nodes per block (512 first-wave independent
// loads for latency cover). g_Opart reads now hit L2 (plain loads).
__global__ void __launch_bounds__(512, 2) k_sw() {
    __shared__ float ysm[2][T_][132];       // raw numerator sums, padded
    __shared__ float linv_s[16];            // [node][t]
    int tid = threadIdx.x;
    int nb2 = blockIdx.x * 2;

    if (tid < 16) {
        int node = tid >> 3, tt = tid & 7;
        int row = tt * N_ + nb2 + node;
        float l = 0.f;
        #pragma unroll
        for (int c = 0; c < JC_; c++) l += g_lpart[c * T_ * N_ + row];
        linv_s[tid] = (l > 0.f) ? (1.0f / l) : 0.0f;   // inert guard
    }

    // 2 nodes x 8t x 32 float4 = 512 positions; one per thread
    {
        int node = tid >> 8;
        int rem  = tid & 255;
        int tt = rem >> 5, d4 = (rem & 31) * 4;
        size_t base = (((size_t)tt * N_) + nb2 + node) * D_ + d4;
        float4 acc = *(const float4*)&g_Opart[base];
        #pragma unroll
        for (int c = 1; c < JC_; c++) {
            float4 v = *(const float4*)&g_Opart[(size_t)c * T_ * N_ * D_ + base];
            acc.x += v.x; acc.y += v.y; acc.z += v.z; acc.w += v.w;
        }
        *(float4*)&ysm[node][tt][d4] = acc;
    }
    __syncthreads();

    if (tid < 128) {
        int node = tid >> 6;
        int p    = tid & 63;
        int tt   = p >> 3, ss = p & 7;
        const float* yt = ysm[node][tt];
        const float* ys = ysm[node][ss];
        float acc = 0.f;
        #pragma unroll
        for (int d4 = 0; d4 < 128; d4 += 4) {
            float4 a = *(const float4*)&yt[d4];
            float4 b = *(const float4*)&ys[d4];
            acc = fmaf(a.x, b.x, acc); acc = fmaf(a.y, b.y, acc);
            acc = fmaf(a.z, b.z, acc); acc = fmaf(a.w, b.w, acc);
        }
        float x = acc * linv_s[node * 8 + tt] * linv_s[node * 8 + ss] * SCALE;
        g_SW[(nb2 + node) * 64 + p] = 1.0f / (1.0f + __expf(-x));   // [j][t*8+s]
    }
}

// ---------------- K2b: pure streaming expand, one output row per block ----------------
// 8192 blocks x 256 threads. Row r = s*N + j is one contiguous 32KB stream;
// t-segments (4KB each) are consecutive. 8 STG.128 per thread, __stcs
// (the 256MB output is genuinely write-once-dead — hint stays).
__global__ void __launch_bounds__(256) k_expand(float* __restrict__ out) {
    int r = blockIdx.x;                     // 0..8191
    int s = r >> 10, j = r & 1023;
    const float* sw = g_SW + j * 64 + s;    // stride 8 over t
    float4* p = (float4*)out + (size_t)r * 2048 + threadIdx.x;
    #pragma unroll
    for (int t = 0; t < T_; t++) {
        float v = __ldg(&sw[t * 8]);
        __stcs(p, make_float4(v, v, v, v));
        p += 256;
    }
}

extern "C" void kernel_launch(void* const* d_in, const int* in_sizes, int n_in,
                              void* d_out, int out_size) {
    const float* raw = (const float*)d_in[0];
    const int*   adj = (const int*)d_in[1];
    float*       out = (float*)d_out;

    static bool attr_set = false;
    if (!attr_set) {
        cudaFuncSetAttribute(k_attn, cudaFuncAttributeMaxDynamicSharedMemorySize, SM_TOT);
        attr_set = true;
    }

    k_cast<<<(T_ * N_ * D_ + 255) / 256, 256>>>(raw);
    k_pack<<<(N_ * N_) / 256, 256>>>(adj);
    k_attn<<<dim3(16, JC_, T_), 128, SM_TOT>>>();
    k_sw<<<N_ / 2, 512>>>();
    k_expand<<<T_ * N_, 256>>>(out);
}

// round 16
// speedup vs baseline: 1.0440x; 1.0440x over previous
#include <cuda_runtime.h>
#include <cuda_bf16.h>
#include <mma.h>
#include <cstdint>
using namespace nvcuda;

#define T_ 8
#define N_ 1024
#define D_ 128
#define JC_ 4                    // j-chunks (split of the attention j loop)
static constexpr float SCALE = 0.08838834764831845f; // 1/sqrt(128)

// ---- scratch (__device__ globals; no allocation allowed) ----
__device__ __align__(16) __nv_bfloat16 g_Xh[T_ * N_ * D_];            // 2 MB
__device__ __align__(16) unsigned      g_adjp[N_ * (N_ / 32)];        // 128 KB bitmask
__device__ __align__(16) __nv_bfloat16 g_Opart[JC_ * T_ * N_ * D_];   // 8 MB partial numerators (bf16)
__device__ __align__(16) float         g_lpart[JC_ * T_ * N_];        // 128 KB partial denominators
__device__ __align__(16) float         g_SW[N_ * T_ * T_];            // 256 KB sigmoid weights

// ---------------- PTX helpers ----------------
__device__ __forceinline__ uint32_t smaddr(const void* p) {
    return (uint32_t)__cvta_generic_to_shared(p);
}
__device__ __forceinline__ void cpa16(uint32_t dst, const void* src) {
    asm volatile("cp.async.cg.shared.global [%0], [%1], 16;" :: "r"(dst), "l"(src));
}
__device__ __forceinline__ void cpa_commit() { asm volatile("cp.async.commit_group;"); }
template <int NN> __device__ __forceinline__ void cpa_wait() {
    asm volatile("cp.async.wait_group %0;" :: "n"(NN));
}
__device__ __forceinline__ void ldsm4(uint32_t& r0, uint32_t& r1, uint32_t& r2, uint32_t& r3,
                                      uint32_t a) {
    asm volatile("ldmatrix.sync.aligned.m8n8.x4.shared.b16 {%0,%1,%2,%3},[%4];"
                 : "=r"(r0), "=r"(r1), "=r"(r2), "=r"(r3) : "r"(a));
}
__device__ __forceinline__ void mma16816(float* c, uint32_t a0, uint32_t a1, uint32_t a2,
                                         uint32_t a3, uint32_t b0, uint32_t b1) {
    asm volatile("mma.sync.aligned.m16n8k16.row.col.f32.bf16.bf16.f32 "
                 "{%0,%1,%2,%3}, {%4,%5,%6,%7}, {%8,%9}, {%0,%1,%2,%3};"
                 : "+f"(c[0]), "+f"(c[1]), "+f"(c[2]), "+f"(c[3])
                 : "r"(a0), "r"(a1), "r"(a2), "r"(a3), "r"(b0), "r"(b1));
}
__device__ __forceinline__ uint32_t packbf(float a, float b) {
    __nv_bfloat162 h = __floats2bfloat162_rn(a, b);
    return *(uint32_t*)&h;
}

// ---------------- K0: fp32 -> bf16 cast ----------------
__global__ void k_cast(const float* __restrict__ x) {
    int i = blockIdx.x * blockDim.x + threadIdx.x;
    if (i < T_ * N_ * D_) g_Xh[i] = __float2bfloat16(x[i]);
}

// ---------------- K0b: pack adj into bitmask ----------------
__global__ void k_pack(const int* __restrict__ adj) {
    int idx = blockIdx.x * blockDim.x + threadIdx.x;   // over N*N
    unsigned m = __ballot_sync(~0u, adj[idx] > 0);
    if ((threadIdx.x & 31) == 0) g_adjp[idx >> 5] = m;
}

// ---------------- K1: fused partial attention (single-buffer Xj, 4 blocks/SM) ----------------
// grid (16, JC_, T_) = 512 blocks, 128 threads. smem 46 KB -> 4 blocks/SM
// -> 592 capacity >= 512: ONE full wave, no tail (63.5KB/3-per-SM left a
// 68-block tail wave). Lost Xj prefetch overlap is covered by 4 co-resident
// blocks. QK in registers (mma.m16n8k16), exp in registers, P->smem, wmma AV.
// smem layout (46080 B):
//   [0      ) Xm  bf16 64x136  17408
//   [17408  ) Xj  bf16 64x136  17408
//   [34816  ) P   bf16 64x72    9216
//   [44032  ) adj u32 64x8      2048
//   epilogue: O f32 64x132 = 33792 reuses [0,33792)
#define SM_XJ   17408
#define SM_P    34816
#define SM_ADJ  44032
#define SM_TOT  46080

__global__ void __launch_bounds__(128, 4) k_attn() {
    extern __shared__ char smraw[];
    __nv_bfloat16* Xms  = (__nv_bfloat16*)smraw;
    __nv_bfloat16* Xjp  = (__nv_bfloat16*)(smraw + SM_XJ);
    __nv_bfloat16* Pts  = (__nv_bfloat16*)(smraw + SM_P);
    unsigned*      adjs = (unsigned*)(smraw + SM_ADJ);
    float*         Osm  = (float*)smraw;    // epilogue only
    uint32_t smXm = smaddr(smraw);
    uint32_t smXj = smXm + SM_XJ;

    int m0 = blockIdx.x * 64;
    int jc = blockIdx.y;
    int t  = blockIdx.z;
    int jbase = jc * (N_ / JC_);            // 256-wide chunk
    int tid = threadIdx.x;
    int w    = tid >> 5;
    int lane = tid & 31;
    const __nv_bfloat16* Xt = g_Xh + (size_t)t * N_ * D_;

    // ---- load Xm tile (plain) + adj bits ----
    #pragma unroll
    for (int q = 0; q < 8; q++) {
        int idx = tid + q * 128;            // 1024 uint4
        int r = idx >> 4, c = (idx & 15) * 8;
        *(uint4*)&Xms[r * 136 + c] = *(const uint4*)&Xt[(m0 + r) * D_ + c];
    }
    #pragma unroll
    for (int q = 0; q < 4; q++) {
        int i = tid + q * 128;              // 512 words
        adjs[i] = g_adjp[(m0 + (i >> 3)) * 32 + jc * 8 + (i & 7)];
    }

    // ---- per-thread fragment constants ----
    int gr = lane >> 2, tc = lane & 3;      // C-frag: rows gr/gr+8, cols 2tc/2tc+1
    int lrow  = lane & 15;
    int lcol8 = 8 * (lane >> 4);
    uint32_t aoffA    = (uint32_t)((16 * w + lrow) * 136 + lcol8) * 2;
    uint32_t aoffBrow = (uint32_t)(lrow * 136 + lcol8) * 2;

    wmma::fragment<wmma::accumulator, 16, 16, 16, float> oacc[4][2];
    #pragma unroll
    for (int a = 0; a < 4; a++)
        #pragma unroll
        for (int b = 0; b < 2; b++) wmma::fill_fragment(oacc[a][b], 0.0f);

    float rs0 = 0.f, rs1 = 0.f;
    const int NIT = (N_ / JC_) / 64;        // 4 j-tiles per chunk

    #pragma unroll 1
    for (int it = 0; it < NIT; it++) {
        __syncthreads();                    // prev AV done -> Xj & P reusable
        int j0 = jbase + it * 64;
        #pragma unroll
        for (int q = 0; q < 8; q++) {       // FULL 1024 uint4 = 64x128 tile
            int idx = tid + q * 128;
            int r = idx >> 4, c = (idx & 15) * 8;
            cpa16(smXj + (uint32_t)(r * 136 + c) * 2, &Xt[(j0 + r) * D_ + c]);
        }
        cpa_commit();
        cpa_wait<0>();
        __syncthreads();                    // Xj visible to all warps

        // ---- QK: S(16x64) in registers ----
        float s[8][4];
        #pragma unroll
        for (int nb = 0; nb < 8; nb++)
            #pragma unroll
            for (int k = 0; k < 4; k++) s[nb][k] = 0.0f;

        #pragma unroll
        for (int ks = 0; ks < 8; ks++) {
            int k0 = ks * 16;
            uint32_t a0, a1, a2, a3;
            ldsm4(a0, a1, a2, a3, smXm + aoffA + (uint32_t)k0 * 2);
            #pragma unroll
            for (int p = 0; p < 4; p++) {
                uint32_t q0, q1, q2, q3;
                ldsm4(q0, q1, q2, q3, smXj + aoffBrow + (uint32_t)(16 * p * 136 + k0) * 2);
                mma16816(s[2 * p],     a0, a1, a2, a3, q0, q2);
                mma16816(s[2 * p + 1], a0, a1, a2, a3, q1, q3);
            }
        }

        // ---- mask + exp + rowsum; P -> smem ----
        {
            int rowE = 16 * w + gr;
            int ar0 = rowE * 8 + it * 2;
            int ar1 = (rowE + 8) * 8 + it * 2;
            unsigned w0a = adjs[ar0], w0b = adjs[ar0 + 1];
            unsigned w1a = adjs[ar1], w1b = adjs[ar1 + 1];
            #pragma unroll
            for (int nb = 0; nb < 8; nb++) {
                int col = 8 * nb + 2 * tc;
                unsigned wa = (nb < 4) ? w0a : w0b;
                unsigned wb = (nb < 4) ? w1a : w1b;
                int sh = col & 31;
                float e0 = ((wa >> sh) & 1u)       ? __expf(fminf(s[nb][0] * SCALE, 30.f)) : 0.f;
                float e1 = ((wa >> (sh + 1)) & 1u) ? __expf(fminf(s[nb][1] * SCALE, 30.f)) : 0.f;
                float f0 = ((wb >> sh) & 1u)       ? __expf(fminf(s[nb][2] * SCALE, 30.f)) : 0.f;
                float f1 = ((wb >> (sh + 1)) & 1u) ? __expf(fminf(s[nb][3] * SCALE, 30.f)) : 0.f;
                rs0 += e0 + e1;
                rs1 += f0 + f1;
                *(__nv_bfloat162*)&Pts[rowE * 72 + col]       = __floats2bfloat162_rn(e0, e1);
                *(__nv_bfloat162*)&Pts[(rowE + 8) * 72 + col] = __floats2bfloat162_rn(f0, f1);
            }
        }
        __syncthreads();                    // P complete for all 64 rows

        // ---- AV: O[:, 32w:+32] += P . Xj ----
        #pragma unroll
        for (int kk = 0; kk < 4; kk++) {
            wmma::fragment<wmma::matrix_b, 16, 16, 16, __nv_bfloat16, wmma::row_major> b0, b1;
            wmma::load_matrix_sync(b0, &Xjp[(kk * 16) * 136 + 32 * w], 136);
            wmma::load_matrix_sync(b1, &Xjp[(kk * 16) * 136 + 32 * w + 16], 136);
            #pragma unroll
            for (int rr = 0; rr < 4; rr++) {
                wmma::fragment<wmma::matrix_a, 16, 16, 16, __nv_bfloat16, wmma::row_major> af;
                wmma::load_matrix_sync(af, &Pts[(16 * rr) * 72 + kk * 16], 72);
                wmma::mma_sync(oacc[rr][0], af, b0, oacc[rr][0]);
                wmma::mma_sync(oacc[rr][1], af, b1, oacc[rr][1]);
            }
        }
    }

    // ---- epilogue: row sums + bf16 partial O ----
    __syncthreads();                        // AV done; Xm region reusable as Osm
    rs0 += __shfl_xor_sync(~0u, rs0, 1); rs0 += __shfl_xor_sync(~0u, rs0, 2);
    rs1 += __shfl_xor_sync(~0u, rs1, 1); rs1 += __shfl_xor_sync(~0u, rs1, 2);
    if (tc == 0) {
        int lbase = (jc * T_ + t) * N_ + m0;
        g_lpart[lbase + 16 * w + gr]     = rs0;
        g_lpart[lbase + 16 * w + gr + 8] = rs1;
    }
    #pragma unroll
    for (int rr = 0; rr < 4; rr++)
        #pragma unroll
        for (int cc = 0; cc < 2; cc++)
            wmma::store_matrix_sync(&Osm[(16 * rr) * 132 + 32 * w + 16 * cc],
                                    oacc[rr][cc], 132, wmma::mem_row_major);
    __syncthreads();
    __nv_bfloat16* Oout = g_Opart + ((size_t)(jc * T_ + t) * N_ + m0) * D_;
    #pragma unroll
    for (int q = 0; q < 8; q++) {
        int idx = tid + q * 128;            // 1024 groups of 8 values
        int r = idx >> 4, c8 = (idx & 15) * 8;
        const float* src = &Osm[r * 132 + c8];
        uint4 v;
        v.x = packbf(src[0], src[1]);
        v.y = packbf(src[2], src[3]);
        v.z = packbf(src[4], src[5]);
        v.w = packbf(src[6], src[7]);
        *(uint4*)&Oout[r * D_ + c8] = v;
    }
}

// ---------------- K2a: reduce + normalize + Gram + sigmoid -> g_SW ----------------
// 512 blocks x 512 threads, two nodes per block; g_Opart is bf16 (half traffic).
__global__ void __launch_bounds__(512, 2) k_sw() {
    __shared__ float ysm[2][T_][132];       // fp32 numerator sums, padded
    __shared__ float linv_s[16];            // [node][t]
    int tid = threadIdx.x;
    int nb2 = blockIdx.x * 2;

    if (tid < 16) {
        int node = tid >> 3, tt = tid & 7;
        int row = tt * N_ + nb2 + node;
        float l = 0.f;
        #pragma unroll
        for (int c = 0; c < JC_; c++) l += g_lpart[c * T_ * N_ + row];
        linv_s[tid] = (l > 0.f) ? (1.0f / l) : 0.0f;   // inert guard
    }

    // 2 nodes x 8t x 32 quads = 512 positions; one per thread (4 bf16 each)
    {
        int node = tid >> 8;
        int rem  = tid & 255;
        int tt = rem >> 5, d4 = (rem & 31) * 4;
        size_t base = (((size_t)tt * N_) + nb2 + node) * D_ + d4;
        float4 acc = make_float4(0.f, 0.f, 0.f, 0.f);
        #pragma unroll
        for (int c = 0; c < JC_; c++) {
            uint2 raw = *(const uint2*)&g_Opart[(size_t)c * T_ * N_ * D_ + base];
            float2 lo = __bfloat1622float2(*(__nv_bfloat162*)&raw.x);
            float2 hi = __bfloat1622float2(*(__nv_bfloat162*)&raw.y);
            acc.x += lo.x; acc.y += lo.y; acc.z += hi.x; acc.w += hi.y;
        }
        *(float4*)&ysm[node][tt][d4] = acc;
    }
    __syncthreads();

    if (tid < 128) {
        int node = tid >> 6;
        int p    = tid & 63;
        int tt   = p >> 3, ss = p & 7;
        const float* yt = ysm[node][tt];
        const float* ys = ysm[node][ss];
        float acc = 0.f;
        #pragma unroll
        for (int d4 = 0; d4 < 128; d4 += 4) {
            float4 a = *(const float4*)&yt[d4];
            float4 b = *(const float4*)&ys[d4];
            acc = fmaf(a.x, b.x, acc); acc = fmaf(a.y, b.y, acc);
            acc = fmaf(a.z, b.z, acc); acc = fmaf(a.w, b.w, acc);
        }
        float x = acc * linv_s[node * 8 + tt] * linv_s[node * 8 + ss] * SCALE;
        g_SW[(nb2 + node) * 64 + p] = 1.0f / (1.0f + __expf(-x));   // [j][t*8+s]
    }
}

// ---------------- K2b: pure streaming expand, one output row per block ----------------
// 8192 blocks x 256 threads. Row r = s*N + j is one contiguous 32KB stream.
__global__ void __launch_bounds__(256) k_expand(float* __restrict__ out) {
    int r = blockIdx.x;                     // 0..8191
    int s = r >> 10, j = r & 1023;
    const float* sw = g_SW + j * 64 + s;    // stride 8 over t
    float4* p = (float4*)out + (size_t)r * 2048 + threadIdx.x;
    #pragma unroll
    for (int t = 0; t < T_; t++) {
        float v = __ldg(&sw[t * 8]);
        __stcs(p, make_float4(v, v, v, v));
        p += 256;
    }
}

extern "C" void kernel_launch(void* const* d_in, const int* in_sizes, int n_in,
                              void* d_out, int out_size) {
    const float* raw = (const float*)d_in[0];
    const int*   adj = (const int*)d_in[1];
    float*       out = (float*)d_out;

    k_cast<<<(T_ * N_ * D_ + 255) / 256, 256>>>(raw);
    k_pack<<<(N_ * N_) / 256, 256>>>(adj);
    k_attn<<<dim3(16, JC_, T_), 128, SM_TOT>>>();
    k_sw<<<N_ / 2, 512>>>();
    k_expand<<<T_ * N_, 256>>>(out);
}